// round 12
// baseline (speedup 1.0000x reference)
#include <cuda_runtime.h>
#include <cstdint>

#define BB 4
#define CC 256
#define CI 128
#define TT 8192
#define NN 4096
#define BNT (BB*TT)

// Scratch (device globals; no allocation allowed)
__device__ float d_theta[BB*CI*TT];   // 16 MB
__device__ float d_phi[BB*CI*NN];     // 8 MB
__device__ float d_g[BB*CI*NN];       // 8 MB
__device__ float d_S[BB*CI*CI];       // 256 KB
__device__ float d_M[BB*CC*CI];       // 512 KB
__device__ float d_wy[BB*CC*TT];      // 32 MB
__device__ float d_sum[CC];
__device__ float d_sumsq[CC];
__device__ float d_scale[CC];
__device__ float d_shift[CC];

// ---------------- tf32 mma.sync helper (raw fp32 bits; BN cancels the
// systematic truncation bias as a per-channel affine distortion) ------------
__device__ __forceinline__ void mma_tf32(float* d, const uint32_t* a, const uint32_t* b) {
    asm("mma.sync.aligned.m16n8k8.row.col.f32.tf32.tf32.f32 "
        "{%0,%1,%2,%3}, {%4,%5,%6,%7}, {%8,%9}, {%0,%1,%2,%3};"
        : "+f"(d[0]), "+f"(d[1]), "+f"(d[2]), "+f"(d[3])
        : "r"(a[0]), "r"(a[1]), "r"(a[2]), "r"(a[3]), "r"(b[0]), "r"(b[1]));
}

// ---------------- cp.async helpers ------------------------------------------
__device__ __forceinline__ uint32_t smem_u32(const void* p) {
    uint32_t a;
    asm("{ .reg .u64 t; cvta.to.shared.u64 t, %1; cvt.u32.u64 %0, t; }" : "=r"(a) : "l"(p));
    return a;
}
__device__ __forceinline__ void cp16(uint32_t dst, const void* src) {
    asm volatile("cp.async.cg.shared.global [%0], [%1], 16;" :: "r"(dst), "l"(src));
}
#define CP_COMMIT() asm volatile("cp.async.commit_group;" ::: "memory")
#define CP_WAIT1()  asm volatile("cp.async.wait_group 1;" ::: "memory")
#define CP_WAIT0()  asm volatile("cp.async.wait_group 0;" ::: "memory")

// SMEM geometry: A chunk 128 rows x 32 k (row-major, pad 4); B chunk
// 32 k x 128 cols (pad 8). Double-buffered.
//   A frag loads: bank = (4*lr + lq + 8ks) % 32  -> conflict-free
//   B frag loads: bank = (8*lq + lr) % 32        -> conflict-free
//   gram B (row-major like A): bank = (4*lr + lq) -> conflict-free
#define RPA 36
#define RPB 136
#define ASZ (128*RPA)          // 4608 u32
#define BSZ (32*RPB)           // 4352 u32
#define STG_C (ASZ + BSZ)      // 8960 u32
#define SMEM_CONV (2*STG_C*4)  // 71680 B
#define STG_S (ASZ + ASZ)      // 9216 u32
#define SMEM_S (2*STG_S*4)     // 73728 B
#define STG_2 (2*ASZ + BSZ)    // 13568 u32 (phi+g merged)
#define SMEM_C2 (2*STG_2*4)    // 108544 B

// Stage 128 rows x 32 floats (A-style), cp.async.
__device__ __forceinline__ void stage128x32(uint32_t dstb, const float* __restrict__ src,
                                            int lds, int koff, int tid) {
#pragma unroll
    for (int i = 0; i < 4; i++) {
        int fid = i * 256 + tid;        // 0..1023
        int r = fid >> 3, q = fid & 7;
        cp16(dstb + (uint32_t)(r * RPA + q * 4) * 4,
             src + (size_t)r * lds + koff + q * 4);
    }
}
// Stage 32 k-rows x 128 floats (B-style), cp.async.
__device__ __forceinline__ void stage32x128(uint32_t dstb, const float* __restrict__ src,
                                            int lds, int koff, int t0, int tid) {
#pragma unroll
    for (int i = 0; i < 4; i++) {
        int fid = i * 256 + tid;        // 0..1023
        int k = fid >> 5, t4 = (fid & 31) << 2;
        cp16(dstb + (uint32_t)(k * RPB + t4) * 4,
             src + (size_t)(koff + k) * lds + t0 + t4);
    }
}

// Load the 4 A-fragment regs for (warp-row block ro, ks) from A-style smem.
__device__ __forceinline__ void ldA(uint32_t* a, const uint32_t* As, int ro,
                                    int k0, int lq, int lr) {
    a[0] = As[(ro + lr) * RPA + k0 + lq];
    a[1] = As[(ro + lr + 8) * RPA + k0 + lq];
    a[2] = As[(ro + lr) * RPA + k0 + 4 + lq];
    a[3] = As[(ro + lr + 8) * RPA + k0 + 4 + lq];
}

// ---------------------------------------------------------------------------
// K0: zero accumulators (S, M, sum, sumsq).
// ---------------------------------------------------------------------------
__global__ void k_init() {
    int i = blockIdx.x * blockDim.x + threadIdx.x;   // 0..65535
    if (i < BB*CI*CI) d_S[i] = 0.0f;
    d_M[2*i]   = 0.0f;
    d_M[2*i+1] = 0.0f;
    if (i < CC) { d_sum[i] = 0.0f; d_sumsq[i] = 0.0f; }
}

// ---------------------------------------------------------------------------
// K1a: theta conv via tf32 mma.sync + cp.async double buffer.
// Block: 128 o x 128 t, K=256 in 8 chunks of 32.
// ---------------------------------------------------------------------------
__global__ void __launch_bounds__(256, 2) k_conv_th(
    const float* __restrict__ x,
    const float* __restrict__ Wt, const float* __restrict__ bt)
{
    extern __shared__ uint32_t smem[];
    const uint32_t smb = smem_u32(smem);

    const int tid = threadIdx.x;
    const int warp = tid >> 5, lane = tid & 31;
    const int wo = warp >> 1, wt = warp & 1;
    const int b  = blockIdx.z;
    const int t0 = blockIdx.x * 128;
    const float* xb = x + (size_t)b * CC * TT;

    float acc[2][8][4];
#pragma unroll
    for (int mi = 0; mi < 2; mi++)
#pragma unroll
        for (int nt = 0; nt < 8; nt++)
#pragma unroll
            for (int j = 0; j < 4; j++) acc[mi][nt][j] = 0.0f;

    const int lq = lane & 3, lr = lane >> 2;
    const int NC = 8;

    stage128x32(smb, Wt, CC, 0, tid);
    stage32x128(smb + ASZ * 4, xb, TT, 0, t0, tid);
    CP_COMMIT();

    for (int kc = 0; kc < NC; kc++) {
        if (kc + 1 < NC) {
            uint32_t ab = smb + (uint32_t)(((kc + 1) & 1) * STG_C) * 4;
            stage128x32(ab, Wt, CC, (kc + 1) * 32, tid);
            stage32x128(ab + ASZ * 4, xb, TT, (kc + 1) * 32, t0, tid);
            CP_COMMIT();
            CP_WAIT1();
        } else {
            CP_WAIT0();
        }
        __syncthreads();
        const uint32_t* As = smem + (kc & 1) * STG_C;
        const uint32_t* Bs = As + ASZ;
#pragma unroll
        for (int ks = 0; ks < 4; ks++) {
            int k0 = ks * 8;
            uint32_t a[2][4], bf[8][2];
#pragma unroll
            for (int mi = 0; mi < 2; mi++)
                ldA(a[mi], As, (wo * 2 + mi) * 16, k0, lq, lr);
            int tb = wt * 64 + lr;
#pragma unroll
            for (int nt = 0; nt < 8; nt++) {
                bf[nt][0] = Bs[(k0 + lq) * RPB + tb + nt * 8];
                bf[nt][1] = Bs[(k0 + 4 + lq) * RPB + tb + nt * 8];
            }
#pragma unroll
            for (int mi = 0; mi < 2; mi++)
#pragma unroll
                for (int nt = 0; nt < 8; nt++)
                    mma_tf32(acc[mi][nt], a[mi], bf[nt]);
        }
        __syncthreads();
    }

    float* dst = d_theta + (size_t)b * CI * TT;
#pragma unroll
    for (int mi = 0; mi < 2; mi++) {
        int o1 = wo * 32 + mi * 16 + lr;
        int o2 = o1 + 8;
        float bz1 = bt[o1], bz2 = bt[o2];
#pragma unroll
        for (int nt = 0; nt < 8; nt++) {
            int t = t0 + wt * 64 + nt * 8 + 2 * lq;
            *(float2*)(dst + (size_t)o1 * TT + t) =
                make_float2(acc[mi][nt][0] + bz1, acc[mi][nt][1] + bz1);
            *(float2*)(dst + (size_t)o2 * TT + t) =
                make_float2(acc[mi][nt][2] + bz2, acc[mi][nt][3] + bz2);
        }
    }
}

// ---------------------------------------------------------------------------
// K1b: MERGED phi+g convs. One block computes BOTH 128-o tiles for its
// 128-t range: x staged once, B fragments loaded once, 2x MMA.
// ---------------------------------------------------------------------------
__global__ void __launch_bounds__(256, 1) k_conv_pg(
    const float* __restrict__ x,
    const float* __restrict__ Wp, const float* __restrict__ bp,
    const float* __restrict__ Wg, const float* __restrict__ bg)
{
    extern __shared__ uint32_t smem[];
    const uint32_t smb = smem_u32(smem);

    const int tid = threadIdx.x;
    const int warp = tid >> 5, lane = tid & 31;
    const int wo = warp >> 1, wt = warp & 1;
    const int b  = blockIdx.z;
    const int t0 = blockIdx.x * 128;
    const float* xb = x + (size_t)b * CC * TT;

    float accP[2][8][4], accG[2][8][4];
#pragma unroll
    for (int mi = 0; mi < 2; mi++)
#pragma unroll
        for (int nt = 0; nt < 8; nt++)
#pragma unroll
            for (int j = 0; j < 4; j++) { accP[mi][nt][j] = 0.0f; accG[mi][nt][j] = 0.0f; }

    const int lq = lane & 3, lr = lane >> 2;
    const int NC = 8;

    // stage layout per stage: [Ap | Ag | B]
    stage128x32(smb, Wp, CC, 0, tid);
    stage128x32(smb + ASZ * 4, Wg, CC, 0, tid);
    stage32x128(smb + 2 * ASZ * 4, xb, TT, 0, t0, tid);
    CP_COMMIT();

    for (int kc = 0; kc < NC; kc++) {
        if (kc + 1 < NC) {
            uint32_t ab = smb + (uint32_t)(((kc + 1) & 1) * STG_2) * 4;
            stage128x32(ab, Wp, CC, (kc + 1) * 32, tid);
            stage128x32(ab + ASZ * 4, Wg, CC, (kc + 1) * 32, tid);
            stage32x128(ab + 2 * ASZ * 4, xb, TT, (kc + 1) * 32, t0, tid);
            CP_COMMIT();
            CP_WAIT1();
        } else {
            CP_WAIT0();
        }
        __syncthreads();
        const uint32_t* Ap = smem + (kc & 1) * STG_2;
        const uint32_t* Ag = Ap + ASZ;
        const uint32_t* Bs = Ap + 2 * ASZ;
#pragma unroll
        for (int ks = 0; ks < 4; ks++) {
            int k0 = ks * 8;
            uint32_t bf[8][2];
            int tb = wt * 64 + lr;
#pragma unroll
            for (int nt = 0; nt < 8; nt++) {
                bf[nt][0] = Bs[(k0 + lq) * RPB + tb + nt * 8];
                bf[nt][1] = Bs[(k0 + 4 + lq) * RPB + tb + nt * 8];
            }
#pragma unroll
            for (int mi = 0; mi < 2; mi++) {
                uint32_t a[4];
                ldA(a, Ap, (wo * 2 + mi) * 16, k0, lq, lr);
#pragma unroll
                for (int nt = 0; nt < 8; nt++)
                    mma_tf32(accP[mi][nt], a, bf[nt]);
            }
#pragma unroll
            for (int mi = 0; mi < 2; mi++) {
                uint32_t a[4];
                ldA(a, Ag, (wo * 2 + mi) * 16, k0, lq, lr);
#pragma unroll
                for (int nt = 0; nt < 8; nt++)
                    mma_tf32(accG[mi][nt], a, bf[nt]);
            }
        }
        __syncthreads();
    }

    float* dstP = d_phi + (size_t)b * CI * NN;
    float* dstG = d_g   + (size_t)b * CI * NN;
#pragma unroll
    for (int mi = 0; mi < 2; mi++) {
        int o1 = wo * 32 + mi * 16 + lr;
        int o2 = o1 + 8;
        float p1 = bp[o1], p2 = bp[o2];
        float g1 = bg[o1], g2 = bg[o2];
#pragma unroll
        for (int nt = 0; nt < 8; nt++) {
            int n = (t0 >> 1) + wt * 32 + nt * 4 + lq;
            dstP[(size_t)o1 * NN + n] = fmaxf(accP[mi][nt][0], accP[mi][nt][1]) + p1;
            dstP[(size_t)o2 * NN + n] = fmaxf(accP[mi][nt][2], accP[mi][nt][3]) + p2;
            dstG[(size_t)o1 * NN + n] = fmaxf(accG[mi][nt][0], accG[mi][nt][1]) + g1;
            dstG[(size_t)o2 * NN + n] = fmaxf(accG[mi][nt][2], accG[mi][nt][3]) + g2;
        }
    }
}

// ---------------------------------------------------------------------------
// K2: S[b,a,ci] = sum_n phi[b,a,n]*g[b,ci,n], tf32 mma + cp.async pipeline.
// Split-K: 16 slabs of 256 n (8 chunks of 32). Atomic reduce into d_S.
// ---------------------------------------------------------------------------
__global__ void __launch_bounds__(256, 2) k_S_hmma()
{
    extern __shared__ uint32_t smem[];
    const uint32_t smb = smem_u32(smem);

    const int tid = threadIdx.x;
    const int warp = tid >> 5, lane = tid & 31;
    const int wo = warp >> 1, wt = warp & 1;
    const int b  = blockIdx.y;
    const int n0 = blockIdx.x * 256;

    const float* P = d_phi + (size_t)b * CI * NN;
    const float* G = d_g   + (size_t)b * CI * NN;

    float acc[2][8][4];
#pragma unroll
    for (int mi = 0; mi < 2; mi++)
#pragma unroll
        for (int nt = 0; nt < 8; nt++)
#pragma unroll
            for (int j = 0; j < 4; j++) acc[mi][nt][j] = 0.0f;

    const int lq = lane & 3, lr = lane >> 2;
    const int NC = 8;

    stage128x32(smb, P, NN, n0, tid);
    stage128x32(smb + ASZ * 4, G, NN, n0, tid);
    CP_COMMIT();

    for (int kc = 0; kc < NC; kc++) {
        if (kc + 1 < NC) {
            uint32_t ab = smb + (uint32_t)(((kc + 1) & 1) * STG_S) * 4;
            stage128x32(ab, P, NN, n0 + (kc + 1) * 32, tid);
            stage128x32(ab + ASZ * 4, G, NN, n0 + (kc + 1) * 32, tid);
            CP_COMMIT();
            CP_WAIT1();
        } else {
            CP_WAIT0();
        }
        __syncthreads();
        const uint32_t* As  = smem + (kc & 1) * STG_S;
        const uint32_t* Bs2 = As + ASZ;
#pragma unroll
        for (int ks = 0; ks < 4; ks++) {
            int k0 = ks * 8;
            uint32_t a[2][4], bf[8][2];
#pragma unroll
            for (int mi = 0; mi < 2; mi++)
                ldA(a[mi], As, (wo * 2 + mi) * 16, k0, lq, lr);
#pragma unroll
            for (int nt = 0; nt < 8; nt++) {
                int n = wt * 64 + nt * 8 + lr;
                bf[nt][0] = Bs2[n * RPA + k0 + lq];
                bf[nt][1] = Bs2[n * RPA + k0 + 4 + lq];
            }
#pragma unroll
            for (int mi = 0; mi < 2; mi++)
#pragma unroll
                for (int nt = 0; nt < 8; nt++)
                    mma_tf32(acc[mi][nt], a[mi], bf[nt]);
        }
        __syncthreads();
    }

    float* Sp = d_S + (size_t)b * CI * CI;
#pragma unroll
    for (int mi = 0; mi < 2; mi++) {
        int a1 = wo * 32 + mi * 16 + lr;
        int a2 = a1 + 8;
#pragma unroll
        for (int nt = 0; nt < 8; nt++) {
            int ci = wt * 64 + nt * 8 + 2 * lq;
            atomicAdd(&Sp[(size_t)a1 * CI + ci],     acc[mi][nt][0]);
            atomicAdd(&Sp[(size_t)a1 * CI + ci + 1], acc[mi][nt][1]);
            atomicAdd(&Sp[(size_t)a2 * CI + ci],     acc[mi][nt][2]);
            atomicAdd(&Sp[(size_t)a2 * CI + ci + 1], acc[mi][nt][3]);
        }
    }
}

// ---------------------------------------------------------------------------
// K3: M[b,o,a] = (1/N) * sum_k w_w[o,k] * S[b,a,k]. Split-k(4) SMEM GEMM.
// Grid: 512 = b(4) x o-tile(8) x a-tile(4) x k-quarter(4). atomicAdd.
// ---------------------------------------------------------------------------
__global__ __launch_bounds__(256) void k_M2(const float* __restrict__ ww)
{
    __shared__ float ws[32][33];
    __shared__ float ss[32][33];

    const int tid = threadIdx.x;
    const int b  = blockIdx.x >> 7;
    const int ob = (blockIdx.x >> 4) & 7;
    const int ab = (blockIdx.x >> 2) & 3;
    const int kh = (blockIdx.x & 3) * 32;

    {
        int r = tid >> 3, c4 = tid & 7;    // 256 threads: 32 rows x 8 float4
        float4 v = *(const float4*)(ww + (size_t)(ob * 32 + r) * CI + kh + 4 * c4);
        ws[r][4*c4+0] = v.x; ws[r][4*c4+1] = v.y; ws[r][4*c4+2] = v.z; ws[r][4*c4+3] = v.w;
        float4 u = *(const float4*)(d_S + (size_t)b * CI * CI + (size_t)(ab * 32 + r) * CI + kh + 4 * c4);
        ss[r][4*c4+0] = u.x; ss[r][4*c4+1] = u.y; ss[r][4*c4+2] = u.z; ss[r][4*c4+3] = u.w;
    }
    __syncthreads();

    const int ty = tid >> 3;
    const int tx = tid & 7;
    float acc[4] = {0.f, 0.f, 0.f, 0.f};
#pragma unroll
    for (int k = 0; k < 32; k++) {
        float wv = ws[ty][k];
#pragma unroll
        for (int j = 0; j < 4; j++) acc[j] = fmaf(wv, ss[4*tx+j][k], acc[j]);
    }
    const float invN = 1.0f / NN;
    float* Mp = d_M + (size_t)b * CC * CI + (size_t)(ob * 32 + ty) * CI + ab * 32 + 4 * tx;
#pragma unroll
    for (int j = 0; j < 4; j++) atomicAdd(&Mp[j], acc[j] * invN);
}

// ---------------------------------------------------------------------------
// K4: wy = M @ theta + w_b via tf32 mma + cp.async pipeline; fused BN sums.
// ---------------------------------------------------------------------------
__global__ void __launch_bounds__(256, 2) k_wy_hmma(const float* __restrict__ wb)
{
    extern __shared__ uint32_t smem[];
    const uint32_t smb = smem_u32(smem);

    const int tid = threadIdx.x;
    const int warp = tid >> 5, lane = tid & 31;
    const int wo = warp >> 1, wt = warp & 1;
    const int b  = blockIdx.z;
    const int o0 = blockIdx.y * 128;
    const int t0 = blockIdx.x * 128;

    const float* Mp = d_M + (size_t)b * CC * CI + (size_t)o0 * CI;
    const float* Th = d_theta + (size_t)b * CI * TT;

    float acc[2][8][4];
#pragma unroll
    for (int mi = 0; mi < 2; mi++)
#pragma unroll
        for (int nt = 0; nt < 8; nt++)
#pragma unroll
            for (int j = 0; j < 4; j++) acc[mi][nt][j] = 0.0f;

    const int lq = lane & 3, lr = lane >> 2;
    const int NC = 4;

    stage128x32(smb, Mp, CI, 0, tid);
    stage32x128(smb + ASZ * 4, Th, TT, 0, t0, tid);
    CP_COMMIT();

    for (int kc = 0; kc < NC; kc++) {
        if (kc + 1 < NC) {
            uint32_t ab = smb + (uint32_t)(((kc + 1) & 1) * STG_C) * 4;
            stage128x32(ab, Mp, CI, (kc + 1) * 32, tid);
            stage32x128(ab + ASZ * 4, Th, TT, (kc + 1) * 32, t0, tid);
            CP_COMMIT();
            CP_WAIT1();
        } else {
            CP_WAIT0();
        }
        __syncthreads();
        const uint32_t* As = smem + (kc & 1) * STG_C;
        const uint32_t* Bs = As + ASZ;
#pragma unroll
        for (int ks = 0; ks < 4; ks++) {
            int k0 = ks * 8;
            uint32_t a[2][4], bf[8][2];
#pragma unroll
            for (int mi = 0; mi < 2; mi++)
                ldA(a[mi], As, (wo * 2 + mi) * 16, k0, lq, lr);
            int tb = wt * 64 + lr;
#pragma unroll
            for (int nt = 0; nt < 8; nt++) {
                bf[nt][0] = Bs[(k0 + lq) * RPB + tb + nt * 8];
                bf[nt][1] = Bs[(k0 + 4 + lq) * RPB + tb + nt * 8];
            }
#pragma unroll
            for (int mi = 0; mi < 2; mi++)
#pragma unroll
                for (int nt = 0; nt < 8; nt++)
                    mma_tf32(acc[mi][nt], a[mi], bf[nt]);
        }
        __syncthreads();
    }

    float* wyp = d_wy + (size_t)b * CC * TT;
#pragma unroll
    for (int mi = 0; mi < 2; mi++) {
        int o1 = o0 + wo * 32 + mi * 16 + lr;
        int o2 = o1 + 8;
        float bz1 = wb[o1], bz2 = wb[o2];
        float s1 = 0.f, q1 = 0.f, s2 = 0.f, q2 = 0.f;
#pragma unroll
        for (int nt = 0; nt < 8; nt++) {
            int t = t0 + wt * 64 + nt * 8 + 2 * lq;
            float v0 = acc[mi][nt][0] + bz1, v1 = acc[mi][nt][1] + bz1;
            float v2 = acc[mi][nt][2] + bz2, v3 = acc[mi][nt][3] + bz2;
            s1 += v0 + v1; q1 = fmaf(v0, v0, q1); q1 = fmaf(v1, v1, q1);
            s2 += v2 + v3; q2 = fmaf(v2, v2, q2); q2 = fmaf(v3, v3, q2);
            *(float2*)(wyp + (size_t)o1 * TT + t) = make_float2(v0, v1);
            *(float2*)(wyp + (size_t)o2 * TT + t) = make_float2(v2, v3);
        }
#pragma unroll
        for (int off = 1; off < 4; off <<= 1) {
            s1 += __shfl_xor_sync(0xffffffffu, s1, off);
            q1 += __shfl_xor_sync(0xffffffffu, q1, off);
            s2 += __shfl_xor_sync(0xffffffffu, s2, off);
            q2 += __shfl_xor_sync(0xffffffffu, q2, off);
        }
        if (lq == 0) {
            atomicAdd(&d_sum[o1], s1);
            atomicAdd(&d_sumsq[o1], q1);
            atomicAdd(&d_sum[o2], s2);
            atomicAdd(&d_sumsq[o2], q2);
        }
    }
}

// ---------------------------------------------------------------------------
// K5: finalize BN statistics.
// ---------------------------------------------------------------------------
__global__ void k_stats(const float* __restrict__ gamma, const float* __restrict__ beta)
{
    int o = threadIdx.x;
    if (o < CC) {
        float mean = d_sum[o]   * (1.0f / BNT);
        float var  = d_sumsq[o] * (1.0f / BNT) - mean * mean;
        float sc   = gamma[o] * rsqrtf(var + 1e-5f);
        d_scale[o] = sc;
        d_shift[o] = beta[o] - mean * sc;
    }
}

// ---------------------------------------------------------------------------
// K6: out = scale[o]*wy + shift[o] + x
// ---------------------------------------------------------------------------
__global__ __launch_bounds__(256) void k_out(const float* __restrict__ x,
                                             float* __restrict__ out)
{
    size_t i4 = (size_t)blockIdx.x * 256 + threadIdx.x;
    int o = (int)((i4 >> 11) & 255);
    float sc = d_scale[o], sh = d_shift[o];
    float4 w  = *((const float4*)d_wy + i4);
    float4 xv = *((const float4*)x + i4);
    float4 r;
    r.x = fmaf(sc, w.x, sh) + xv.x;
    r.y = fmaf(sc, w.y, sh) + xv.y;
    r.z = fmaf(sc, w.z, sh) + xv.z;
    r.w = fmaf(sc, w.w, sh) + xv.w;
    ((float4*)out)[i4] = r;
}

// ---------------------------------------------------------------------------
// Launch: two-stream fork/join (graph-capturable).
//   s1 (high prio): init -> conv_pg (merged) -> S -> M
//   s0 (default)  : conv_th  [backfills SMs while S/M run]
//   join          : wy -> stats -> out
// ---------------------------------------------------------------------------
extern "C" void kernel_launch(void* const* d_in, const int* in_sizes, int n_in,
                              void* d_out, int out_size)
{
    const float* x     = (const float*)d_in[0];
    const float* tw    = (const float*)d_in[1];
    const float* tb    = (const float*)d_in[2];
    const float* pw    = (const float*)d_in[3];
    const float* pb    = (const float*)d_in[4];
    const float* gw    = (const float*)d_in[5];
    const float* gb    = (const float*)d_in[6];
    const float* ww    = (const float*)d_in[7];
    const float* wb    = (const float*)d_in[8];
    const float* gamma = (const float*)d_in[9];
    const float* beta  = (const float*)d_in[10];
    float* out = (float*)d_out;

    static cudaStream_t s1 = nullptr;
    static cudaEvent_t eF = nullptr, eJ = nullptr;
    static int init_done = 0;
    if (!init_done) {
        cudaFuncSetAttribute(k_conv_th, cudaFuncAttributeMaxDynamicSharedMemorySize, SMEM_CONV);
        cudaFuncSetAttribute(k_conv_pg, cudaFuncAttributeMaxDynamicSharedMemorySize, SMEM_C2);
        cudaFuncSetAttribute(k_S_hmma,  cudaFuncAttributeMaxDynamicSharedMemorySize, SMEM_S);
        cudaFuncSetAttribute(k_wy_hmma, cudaFuncAttributeMaxDynamicSharedMemorySize, SMEM_CONV);
        int lo, hi;
        cudaDeviceGetStreamPriorityRange(&lo, &hi);
        cudaStreamCreateWithPriority(&s1, cudaStreamNonBlocking, hi);
        cudaEventCreateWithFlags(&eF, cudaEventDisableTiming);
        cudaEventCreateWithFlags(&eJ, cudaEventDisableTiming);
        init_done = 1;
    }

    // Fork: s1 branches off the main (captured) stream.
    cudaEventRecord(eF, 0);
    cudaStreamWaitEvent(s1, eF, 0);

    // s1 chain: init, merged phi+g conv, S, M.
    k_init<<<256, 256, 0, s1>>>();
    k_conv_pg<<<dim3(TT / 128, 1, BB), 256, SMEM_C2, s1>>>(x, pw, pb, gw, gb);
    k_S_hmma<<<dim3(16, BB), 256, SMEM_S, s1>>>();
    k_M2<<<512, 256, 0, s1>>>(ww);
    cudaEventRecord(eJ, s1);

    // main stream: theta conv runs concurrently (backfills idle SMs).
    k_conv_th<<<dim3(TT / 128, 1, BB), 256, SMEM_CONV>>>(x, tw, tb);

    // Join, then the dependent tail.
    cudaStreamWaitEvent(0, eJ, 0);
    k_wy_hmma<<<dim3(TT / 128, 2, BB), 256, SMEM_CONV>>>(wb);
    k_stats<<<1, 256>>>(gamma, beta);
    k_out<<<8192, 256>>>(x, out);
}